// round 1
// baseline (speedup 1.0000x reference)
#include <cuda_runtime.h>
#include <cuda_bf16.h>
#include <math.h>

// Problem constants
#define BB 4
#define CC 64
#define HH 128
#define WW 128
#define EE 32
#define HW (HH*WW)            // 16384
#define NPIX (BB*HW)          // 65536
#define NASSIGN (NPIX*2)      // 131072
#define WPERE (9*CC*CC)       // 36864 floats per expert (transposed)

// Conv kernel config
#define GP 14                 // groups per CTA
#define CONV_GRID 296         // 296*14 = 4144 >= max total groups (4128)
#define CONV_THREADS 448      // 14 warps
#define CONV_SMEM_FLOATS (WPERE + 64)   // weights + bias
#define CONV_SMEM_BYTES (CONV_SMEM_FLOATS * 4)

// -------- device scratch (no allocations allowed) --------
__device__ float g_xT[NPIX * CC];          // x channels-last [B][H][W][C]
__device__ float g_wT[EE * WPERE];         // weights [E][tap][ci][co]
__device__ int   g_top_idx[NPIX * 2];
__device__ float g_top_w[NPIX * 2];
__device__ int   g_cnt[EE];
__device__ int   g_base[EE];
__device__ int   g_cursor[EE];
__device__ int   g_groupStart[EE + 1];
__device__ int   g_listPix[NASSIGN];
__device__ float g_listW[NASSIGN];

// -------- init: zero output + counters --------
__global__ void k_init(float* out, int n) {
    int i = blockIdx.x * blockDim.x + threadIdx.x;
    if (i < n) out[i] = 0.0f;
    if (blockIdx.x == 0 && threadIdx.x < EE) {
        g_cnt[threadIdx.x] = 0;
        g_cursor[threadIdx.x] = 0;
    }
}

// -------- transpose x: [B][C][H][W] -> [B][HW][C] --------
__global__ void k_tx(const float* __restrict__ x) {
    __shared__ float s[CC][33];
    int b = blockIdx.y;
    int hw0 = blockIdx.x * 32;
    int tx = threadIdx.x;      // 0..31
    int ty = threadIdx.y;      // 0..7
    for (int c = ty; c < CC; c += 8)
        s[c][tx] = x[((size_t)(b * CC + c) << 14) + hw0 + tx];
    __syncthreads();
    int t = ty * 32 + tx;
    for (int k = t; k < 32 * CC; k += 256) {
        int hw = k >> 6, c = k & 63;
        g_xT[((size_t)(b * HW + hw0 + hw) << 6) + c] = s[c][hw];
    }
}

// -------- transpose weights: [E][co][ci][3][3] -> [E][tap][ci][co] --------
__global__ void k_tw(const float* __restrict__ w) {
    int i = blockIdx.x * 256 + threadIdx.x;
    if (i >= EE * WPERE) return;
    int co = i & 63;
    int ci = (i >> 6) & 63;
    int te = i >> 12;          // e*9 + t
    int t = te % 9;
    int e = te / 9;
    g_wT[i] = w[(((e << 6) | co) * 64 + ci) * 9 + t];
}

// -------- gate: logits, top-2, softmax, counts --------
__global__ void k_gate(const float* __restrict__ x,
                       const float* __restrict__ gw,
                       const float* __restrict__ gb) {
    __shared__ float gws[EE * CC];
    __shared__ float gbs[EE];
    int tid = threadIdx.x;
    for (int i = tid; i < EE * CC; i += 256) gws[i] = gw[i];
    if (tid < EE) gbs[tid] = gb[tid];
    __syncthreads();

    int pix = blockIdx.x * 256 + tid;
    int b = pix >> 14, hw = pix & (HW - 1);

    float lg[EE];
#pragma unroll
    for (int e = 0; e < EE; e++) lg[e] = gbs[e];

    const float* xp = x + ((size_t)b << 20) + hw;
#pragma unroll 4
    for (int c = 0; c < CC; c++) {
        float xv = xp[(size_t)c << 14];
#pragma unroll
        for (int e = 0; e < EE; e++) lg[e] = fmaf(xv, gws[e * CC + c], lg[e]);
    }

    // exact top-2 with first-index-on-tie (matches lax.top_k)
    float v1 = -1e30f; int i1 = 0;
#pragma unroll
    for (int e = 0; e < EE; e++) if (lg[e] > v1) { v1 = lg[e]; i1 = e; }
    float v2 = -1e30f; int i2 = 0;
#pragma unroll
    for (int e = 0; e < EE; e++) if (e != i1 && lg[e] > v2) { v2 = lg[e]; i2 = e; }

    float d = expf(v2 - v1);
    float s = 1.0f / (1.0f + d);
    g_top_idx[pix * 2]     = i1;
    g_top_idx[pix * 2 + 1] = i2;
    g_top_w[pix * 2]       = s;
    g_top_w[pix * 2 + 1]   = d * s;
    atomicAdd(&g_cnt[i1], 1);
    atomicAdd(&g_cnt[i2], 1);
}

// -------- prefix sums over 32 experts (trivial) --------
__global__ void k_prefix() {
    if (threadIdx.x == 0) {
        int s = 0, g = 0;
        for (int e = 0; e < EE; e++) {
            g_base[e] = s;       s += g_cnt[e];
            g_groupStart[e] = g; g += (g_cnt[e] + 31) >> 5;
        }
        g_groupStart[EE] = g;
    }
}

// -------- scatter assignments into per-expert lists --------
__global__ void k_scatter() {
    int pix = blockIdx.x * 256 + threadIdx.x;
#pragma unroll
    for (int k = 0; k < 2; k++) {
        int e = g_top_idx[pix * 2 + k];
        int pos = atomicAdd(&g_cursor[e], 1);
        int at = g_base[e] + pos;
        g_listPix[at] = pix;
        g_listW[at]   = g_top_w[pix * 2 + k];
    }
}

// -------- main sparse conv --------
__global__ void __launch_bounds__(CONV_THREADS, 1)
k_conv(const float* __restrict__ expert_b, float* __restrict__ out) {
    extern __shared__ float ws[];   // [9][64 ci][64 co] + bias[64]
    const int tid  = threadIdx.x;
    const int warp = tid >> 5;
    const int lane = tid & 31;

    const int total = g_groupStart[EE];
    int g0 = blockIdx.x * GP;
    if (g0 >= total) return;
    int g1 = g0 + GP; if (g1 > total) g1 = total;

    int e = 0;
    while (g_groupStart[e + 1] <= g0) e++;

    bool first = true;
    for (; e < EE; e++) {
        int gs = g_groupStart[e], ge = g_groupStart[e + 1];
        if (gs >= g1) break;
        int ga = g0 > gs ? g0 : gs;
        int gb = g1 < ge ? g1 : ge;
        if (ga >= gb) continue;

        if (!first) __syncthreads();
        first = false;
        {   // stage expert weights (144KB) + bias
            const float4* src = (const float4*)(g_wT + (size_t)e * WPERE);
            float4* dst = (float4*)ws;
            for (int i = tid; i < WPERE / 4; i += CONV_THREADS) dst[i] = src[i];
            if (tid < 64) ws[WPERE + tid] = expert_b[e * 64 + tid];
        }
        __syncthreads();

        const int m  = g_cnt[e];
        const int lb = g_base[e];

        for (int g = ga + warp; g < gb; g += CONV_THREADS / 32) {
            int li = (g - gs) * 32 + lane;
            bool valid = li < m;
            int idx = lb + (valid ? li : 0);
            int pix = g_listPix[idx];
            float gw = g_listW[idx];
            int b  = pix >> 14;
            int hw = pix & (HW - 1);
            int y  = hw >> 7, xw = hw & 127;

            float acc[64];
#pragma unroll
            for (int c = 0; c < 64; c++) acc[c] = 0.0f;

#pragma unroll 1
            for (int t = 0; t < 9; t++) {
                int dy = t / 3 - 1, dx = t % 3 - 1;
                int yy = y + dy, xx = xw + dx;
                if (!valid || (unsigned)yy >= (unsigned)HH || (unsigned)xx >= (unsigned)WW)
                    continue;
                const float4* __restrict__ xp =
                    (const float4*)(g_xT + ((size_t)((b << 14) + (yy << 7) + xx) << 6));
                const float4* __restrict__ wt4 = (const float4*)(ws + t * (CC * CC));
#pragma unroll 2
                for (int c4i = 0; c4i < 16; c4i++) {
                    float4 xv = xp[c4i];
#pragma unroll
                    for (int j = 0; j < 4; j++) {
                        float xs = (j == 0) ? xv.x : (j == 1) ? xv.y : (j == 2) ? xv.z : xv.w;
                        const float4* wr = wt4 + ((c4i * 4 + j) << 4);
#pragma unroll
                        for (int o = 0; o < 16; o++) {
                            float4 wv = wr[o];
                            acc[4 * o + 0] = fmaf(xs, wv.x, acc[4 * o + 0]);
                            acc[4 * o + 1] = fmaf(xs, wv.y, acc[4 * o + 1]);
                            acc[4 * o + 2] = fmaf(xs, wv.z, acc[4 * o + 2]);
                            acc[4 * o + 3] = fmaf(xs, wv.w, acc[4 * o + 3]);
                        }
                    }
                }
            }

            if (valid) {
                float* op = out + ((size_t)b << 20) + hw;
#pragma unroll
                for (int c = 0; c < 64; c++)
                    atomicAdd(op + ((size_t)c << 14), gw * (acc[c] + ws[WPERE + c]));
            }
        }
    }
}

// -------- final relu in place --------
__global__ void k_relu(float* out, int n) {
    int i = blockIdx.x * 256 + threadIdx.x;
    if (i < n) out[i] = fmaxf(out[i], 0.0f);
}

extern "C" void kernel_launch(void* const* d_in, const int* in_sizes, int n_in,
                              void* d_out, int out_size) {
    const float* x        = (const float*)d_in[0];
    const float* expert_w = (const float*)d_in[1];
    const float* expert_b = (const float*)d_in[2];
    const float* gate_w   = (const float*)d_in[3];
    const float* gate_b   = (const float*)d_in[4];
    float* out = (float*)d_out;

    cudaFuncSetAttribute(k_conv, cudaFuncAttributeMaxDynamicSharedMemorySize,
                         CONV_SMEM_BYTES);

    int n = NPIX * CC;   // 4,194,304 output elems

    k_init<<<(n + 255) / 256, 256>>>(out, n);
    k_tx<<<dim3(HW / 32, BB), dim3(32, 8)>>>(x);
    k_tw<<<(EE * WPERE + 255) / 256, 256>>>(expert_w);
    k_gate<<<NPIX / 256, 256>>>(x, gate_w, gate_b);
    k_prefix<<<1, 32>>>();
    k_scatter<<<NPIX / 256, 256>>>();
    k_conv<<<CONV_GRID, CONV_THREADS, CONV_SMEM_BYTES>>>(expert_b, out);
    k_relu<<<(n + 255) / 256, 256>>>(out, n);
}